// round 3
// baseline (speedup 1.0000x reference)
#include <cuda_runtime.h>

#define INC    64
#define OUTC   64
#define KOFF   27
#define NT     128          // output voxels per tile/block
#define BN_EPS 1e-5f

typedef unsigned long long ull;

__device__ int   g_counts[KOFF];
__device__ int   g_lo[KOFF * 3264];      // per-(k,tile) range starts
__device__ float g_sum[OUTC];
__device__ float g_sumsq[OUTC];

// ---------- fp32x2 helpers ----------
static __device__ __forceinline__ ull fma2(ull a, ull b, ull c) {
    ull d;
    asm("fma.rn.f32x2 %0, %1, %2, %3;" : "=l"(d) : "l"(a), "l"(b), "l"(c));
    return d;
}
static __device__ __forceinline__ ull dup2(float x) {
    ull r;
    asm("mov.b64 %0, {%1, %1};" : "=l"(r) : "f"(x));
    return r;
}
static __device__ __forceinline__ void unpack2(ull v, float& lo, float& hi) {
    asm("mov.b64 {%0, %1}, %2;" : "=f"(lo), "=f"(hi) : "l"(v));
}

// ---------- K0: valid-pair counts (mask rows are 1-prefixes) + zero BN stats ----------
__global__ void k_init(const float* __restrict__ mask, int n) {
    int t = threadIdx.x;
    if (t < OUTC) { g_sum[t] = 0.f; g_sumsq[t] = 0.f; }
    if (t < KOFF) {
        const float* m = mask + (size_t)t * n;
        int lo = 0, hi = n;
        while (lo < hi) {
            int mid = (lo + hi) >> 1;
            if (m[mid] > 0.5f) lo = mid + 1; else hi = mid;
        }
        g_counts[t] = lo;
    }
}

// ---------- K1: per-(k,tile) pair-range boundaries (out_idx rows are sorted) ----------
__global__ void k_setup(const int* __restrict__ out_idx, int n, int ntiles) {
    int idx = blockIdx.x * blockDim.x + threadIdx.x;
    int per = ntiles + 1;
    if (idx >= KOFF * per) return;
    int k = idx / per;
    int t = idx - k * per;
    int target = t * NT;
    const int* row = out_idx + (size_t)k * n;
    int lo = 0, hi = g_counts[k];
    while (lo < hi) {
        int mid = (lo + hi) >> 1;
        if (row[mid] < target) lo = mid + 1; else hi = mid;
    }
    g_lo[idx] = lo;
}

// ---------- K2: gather-formulated sparse deconv, smem accumulator, fused stats ----------
// dynamic smem layout:
//   ull   Wsm[64*32]      16KB   W[k] as f32x2 col-pairs
//   float Acc[NT*64]      32KB   output-tile accumulator
//   float Fsm[64*NT]      32KB   gathered feats, transposed [inc][pair]
//   int   dl[NT]                 local dst row per pair
#define SMEM_BYTES (16384 + 32768 + 32768 + 512 + 256)

__global__ __launch_bounds__(256)
void k_gemm(const float* __restrict__ feats, const float* __restrict__ W,
            const int* __restrict__ in_idx, const int* __restrict__ out_idx,
            float* __restrict__ out, int n, int ntiles)
{
    extern __shared__ char smraw[];
    ull*   Wsm = (ull*)smraw;                       // [64][32]
    float* Acc = (float*)(smraw + 16384);           // [NT][64]
    float* Fsm = (float*)(smraw + 16384 + 32768);   // [64][NT]
    int*   dl  = (int*)(smraw + 16384 + 32768 + 32768);

    const int tile  = blockIdx.x;
    const int tbase = tile * NT;
    const int tid   = threadIdx.x;
    const int w     = tid >> 5;
    const int lane  = tid & 31;
    const int ph    = lane >> 4;          // half-warp: which 4 pairs of the 8-chunk
    const int cl    = (lane & 15) * 4;    // 4 contiguous output cols

    // zero the accumulator
    for (int i = tid; i < NT * OUTC / 4; i += 256)
        ((float4*)Acc)[i] = make_float4(0.f, 0.f, 0.f, 0.f);

    for (int k = 0; k < KOFF; k++) {
        const int lo = g_lo[k * (ntiles + 1) + tile];
        const int hi = g_lo[k * (ntiles + 1) + tile + 1];
        const int np = hi - lo;

        __syncthreads();   // previous compute done before Fsm/dl/Wsm overwritten

        // stage W[k] (ull copy preserves (2c,2c+1) pairing)
        {
            const ull* Wg = (const ull*)(W + (size_t)k * INC * OUTC);
            #pragma unroll
            for (int i = 0; i < 8; i++) Wsm[tid + 256 * i] = Wg[tid + 256 * i];
        }

        // gather: 2 threads per pair, transposed store (conflict-free: p consecutive)
        {
            const int p = tid >> 1;
            const int half = (tid & 1) * 32;
            if (p < np) {
                const size_t pb = (size_t)k * n + lo + p;
                if ((tid & 1) == 0) dl[p] = out_idx[pb] - tbase;
                const int src = in_idx[pb];
                const float4* fr = (const float4*)(feats + (size_t)src * INC + half);
                #pragma unroll
                for (int j = 0; j < 8; j++) {
                    float4 v = fr[j];
                    int c = half + j * 4;
                    Fsm[(c + 0) * NT + p] = v.x;
                    Fsm[(c + 1) * NT + p] = v.y;
                    Fsm[(c + 2) * NT + p] = v.z;
                    Fsm[(c + 3) * NT + p] = v.w;
                }
            }
        }
        __syncthreads();

        // compute: warp chunk = 8 pairs; half-warp owns 4 pairs; lane owns 4 cols
        for (int c0 = w * 8; c0 < np; c0 += 64) {
            const int pb = c0 + ph * 4;
            ull A0 = 0, A1 = 0, A2 = 0, A3 = 0, A4 = 0, A5 = 0, A6 = 0, A7 = 0;

            #pragma unroll 8
            for (int kk = 0; kk < INC; kk++) {
                float4 f = *(const float4*)&Fsm[kk * NT + pb];
                ulonglong2 wv = *(const ulonglong2*)&Wsm[kk * 32 + (lane & 15) * 2];
                ull a0 = dup2(f.x), a1 = dup2(f.y), a2 = dup2(f.z), a3 = dup2(f.w);
                A0 = fma2(a0, wv.x, A0);  A1 = fma2(a0, wv.y, A1);
                A2 = fma2(a1, wv.x, A2);  A3 = fma2(a1, wv.y, A3);
                A4 = fma2(a2, wv.x, A4);  A5 = fma2(a2, wv.y, A5);
                A6 = fma2(a3, wv.x, A6);  A7 = fma2(a3, wv.y, A7);
            }

            // accumulate into smem tile (dsts distinct within k -> race-free)
            ull Ar[8] = {A0, A1, A2, A3, A4, A5, A6, A7};
            #pragma unroll
            for (int i = 0; i < 4; i++) {
                const int p2 = pb + i;
                if (p2 < np) {
                    float* a = &Acc[dl[p2] * OUTC + cl];
                    float x0, x1, x2, x3;
                    unpack2(Ar[2 * i],     x0, x1);
                    unpack2(Ar[2 * i + 1], x2, x3);
                    float4 cur = *(float4*)a;
                    cur.x += x0; cur.y += x1; cur.z += x2; cur.w += x3;
                    *(float4*)a = cur;
                }
            }
        }
    }
    __syncthreads();

    // store tile + fused BN statistics (thread's channels fixed: (i&15)*4)
    float s0 = 0.f, s1 = 0.f, s2 = 0.f, s3 = 0.f;
    float q0 = 0.f, q1 = 0.f, q2 = 0.f, q3 = 0.f;
    for (int i = tid; i < NT * OUTC / 4; i += 256) {
        float4 v = ((float4*)Acc)[i];
        const int r  = i >> 4;
        const int cc = (i & 15) * 4;
        if (tbase + r < n) {
            *(float4*)(out + (size_t)(tbase + r) * OUTC + cc) = v;
            s0 += v.x; s1 += v.y; s2 += v.z; s3 += v.w;
            q0 += v.x * v.x; q1 += v.y * v.y; q2 += v.z * v.z; q3 += v.w * v.w;
        }
    }
    __syncthreads();
    float* ssum = Fsm;        // reuse
    float* ssq  = Fsm + OUTC;
    if (tid < OUTC) { ssum[tid] = 0.f; ssq[tid] = 0.f; }
    __syncthreads();
    const int cg = (tid & 15) * 4;
    atomicAdd(&ssum[cg + 0], s0); atomicAdd(&ssq[cg + 0], q0);
    atomicAdd(&ssum[cg + 1], s1); atomicAdd(&ssq[cg + 1], q1);
    atomicAdd(&ssum[cg + 2], s2); atomicAdd(&ssq[cg + 2], q2);
    atomicAdd(&ssum[cg + 3], s3); atomicAdd(&ssq[cg + 3], q3);
    __syncthreads();
    if (tid < OUTC) {
        atomicAdd(&g_sum[tid],   ssum[tid]);
        atomicAdd(&g_sumsq[tid], ssq[tid]);
    }
}

// ---------- K3: BatchNorm + ReLU ----------
__global__ __launch_bounds__(256)
void k_bn(float4* __restrict__ out,
          const float* __restrict__ gamma, const float* __restrict__ beta,
          int total4, float invN)
{
    const int tid = threadIdx.x;
    const int cg  = (tid & 15) * 4;
    float mean[4], scl[4], bet[4];
    #pragma unroll
    for (int j = 0; j < 4; j++) {
        int c = cg + j;
        float m = g_sum[c] * invN;
        float var = g_sumsq[c] * invN - m * m;
        mean[j] = m;
        scl[j] = rsqrtf(var + BN_EPS) * gamma[c];
        bet[j] = beta[c];
    }
    const int stride = gridDim.x * 256;
    for (int i = blockIdx.x * 256 + tid; i < total4; i += stride) {
        float4 v = out[i];
        v.x = fmaxf((v.x - mean[0]) * scl[0] + bet[0], 0.f);
        v.y = fmaxf((v.y - mean[1]) * scl[1] + bet[1], 0.f);
        v.z = fmaxf((v.z - mean[2]) * scl[2] + bet[2], 0.f);
        v.w = fmaxf((v.w - mean[3]) * scl[3] + bet[3], 0.f);
        out[i] = v;
    }
}

// ---------- launch ----------
extern "C" void kernel_launch(void* const* d_in, const int* in_sizes, int n_in,
                              void* d_out, int out_size)
{
    const float* feats   = (const float*)d_in[0];
    const float* W       = (const float*)d_in[1];
    const float* gamma   = (const float*)d_in[2];
    const float* beta    = (const float*)d_in[3];
    const float* mask    = (const float*)d_in[4];
    const int*   in_idx  = (const int*)d_in[5];
    const int*   out_idx = (const int*)d_in[6];
    float*       out     = (float*)d_out;

    const int n      = in_sizes[0] / INC;
    const int ntiles = (n + NT - 1) / NT;
    const int total4 = (n * OUTC) / 4;

    cudaFuncSetAttribute(k_gemm, cudaFuncAttributeMaxDynamicSharedMemorySize, SMEM_BYTES);

    k_init<<<1, 64>>>(mask, n);
    k_setup<<<(KOFF * (ntiles + 1) + 255) / 256, 256>>>(out_idx, n, ntiles);
    k_gemm<<<ntiles, 256, SMEM_BYTES>>>(feats, W, in_idx, out_idx, out, n, ntiles);
    k_bn<<<2048, 256>>>((float4*)out, gamma, beta, total4, 1.0f / (float)n);
}

// round 4
// speedup vs baseline: 1.4744x; 1.4744x over previous
#include <cuda_runtime.h>

#define INC    64
#define OUTC   64
#define KOFF   27
#define TILE_P 256
#define BN_EPS 1e-5f

typedef unsigned long long ull;

__device__ int   g_counts[KOFF];
__device__ float g_sum[OUTC];
__device__ float g_sumsq[OUTC];

// ---------- fp32x2 helpers ----------
static __device__ __forceinline__ ull fma2(ull a, ull b, ull c) {
    ull d;
    asm("fma.rn.f32x2 %0, %1, %2, %3;" : "=l"(d) : "l"(a), "l"(b), "l"(c));
    return d;
}
static __device__ __forceinline__ void unpack2(ull v, float& lo, float& hi) {
    asm("mov.b64 {%0, %1}, %2;" : "=f"(lo), "=f"(hi) : "l"(v));
}

// ---------- K0: per-offset valid-pair counts + zero BN stats ----------
__global__ void k_init(const float* __restrict__ mask, int n) {
    int t = threadIdx.x;
    if (t < OUTC) { g_sum[t] = 0.f; g_sumsq[t] = 0.f; }
    if (t < KOFF) {
        const float* m = mask + (size_t)t * n;
        int lo = 0, hi = n;
        while (lo < hi) {
            int mid = (lo + hi) >> 1;
            if (m[mid] > 0.5f) lo = mid + 1; else hi = mid;
        }
        g_counts[t] = lo;
    }
}

// ---------- K0b: zero output ----------
__global__ void k_zero(float4* __restrict__ out, int total4) {
    for (int i = blockIdx.x * blockDim.x + threadIdx.x; i < total4;
         i += gridDim.x * blockDim.x)
        out[i] = make_float4(0.f, 0.f, 0.f, 0.f);
}

// ---------- K1: scatter GEMM, broadcast-W / lane-distinct-pairs micro-tile ----------
// dynamic smem:
//   ull   Wdup[64*64]        32KB   Wdup[kk][c] = (W[k][kk][c], W[k][kk][c])
//   float Fsm [64*TILE_P]    64KB   transposed gathered feats [kk][p]
#define SMEM_BYTES (32768 + 65536)

__global__ __launch_bounds__(256)
void k_gemm(const float* __restrict__ feats, const float* __restrict__ W,
            const int* __restrict__ in_idx, const int* __restrict__ out_idx,
            float* __restrict__ out, int n)
{
    extern __shared__ char smraw[];
    ull*   Wdup = (ull*)smraw;              // [64][64]
    float* Fsm  = (float*)(smraw + 32768);  // [64][TILE_P]

    const int k    = blockIdx.y;
    const int base = blockIdx.x * TILE_P;
    const int cnt  = g_counts[k];
    if (base >= cnt) return;
    const int np = min(TILE_P, cnt - base);

    const int tid  = threadIdx.x;
    const int w    = tid >> 5;
    const int lane = tid & 31;

    // stage W[k] duplicated: read float4, write (x,x)(y,y)(z,z)(w,w)
    {
        const float4* Wg = (const float4*)(W + (size_t)k * INC * OUTC);
        #pragma unroll
        for (int i = tid; i < INC * OUTC / 4; i += 256) {
            float4 v = Wg[i];
            float4* dst = (float4*)&Wdup[i * 4];
            dst[0] = make_float4(v.x, v.x, v.y, v.y);
            dst[1] = make_float4(v.z, v.z, v.w, v.w);
        }
    }

    // gather: thread tid <-> pair tid; transposed store, zero-fill padding
    const size_t kbase = (size_t)k * n + base;
    {
        const int p = tid;
        if (p < np) {
            const int src = in_idx[kbase + p];
            const float4* fr = (const float4*)(feats + (size_t)src * INC);
            #pragma unroll
            for (int j = 0; j < 16; j++) {
                float4 v = fr[j];
                Fsm[(4 * j + 0) * TILE_P + p] = v.x;
                Fsm[(4 * j + 1) * TILE_P + p] = v.y;
                Fsm[(4 * j + 2) * TILE_P + p] = v.z;
                Fsm[(4 * j + 3) * TILE_P + p] = v.w;
            }
        } else {
            #pragma unroll
            for (int j = 0; j < INC; j++) Fsm[j * TILE_P + p] = 0.f;
        }
    }
    __syncthreads();

    // micro-tile: warp = 128 pairs x 16 cols; lane = 4 pairs x 16 cols
    const int cg = (w & 3) * 16;              // col-group base
    const int pb = (w >> 2) * 128 + lane * 4; // this lane's 4 pairs
    if (pb < np) {
        ull acc[16][2];
        #pragma unroll
        for (int c = 0; c < 16; c++) { acc[c][0] = 0ull; acc[c][1] = 0ull; }

        const float* fp = &Fsm[pb];
        const ull*   wp = &Wdup[cg];

        #pragma unroll 4
        for (int kk = 0; kk < INC; kk++) {
            // A: 4 pair values, one LDS.128, reinterpreted as 2 packed f32x2
            ulonglong2 a = *(const ulonglong2*)(fp + (size_t)kk * TILE_P);
            // B: 16 dup'd col values, 8 broadcast LDS.128
            #pragma unroll
            for (int j = 0; j < 8; j++) {
                ulonglong2 w2 = *(const ulonglong2*)(wp + kk * 64 + 2 * j);
                acc[2 * j + 0][0] = fma2(a.x, w2.x, acc[2 * j + 0][0]);
                acc[2 * j + 0][1] = fma2(a.y, w2.x, acc[2 * j + 0][1]);
                acc[2 * j + 1][0] = fma2(a.x, w2.y, acc[2 * j + 1][0]);
                acc[2 * j + 1][1] = fma2(a.y, w2.y, acc[2 * j + 1][1]);
            }
        }

        // scatter: per valid pair, 4 x red.global.add.v4 over 16 contiguous cols
        #pragma unroll
        for (int i = 0; i < 4; i++) {
            const int p = pb + i;
            if (p < np) {
                const int pp = i >> 1;
                const int hi = i & 1;
                float v[16];
                #pragma unroll
                for (int c = 0; c < 16; c++) {
                    float lo_, hi_;
                    unpack2(acc[c][pp], lo_, hi_);
                    v[c] = hi ? hi_ : lo_;
                }
                const int dst = out_idx[kbase + p];
                float* o = out + (size_t)dst * OUTC + cg;
                asm volatile("red.global.add.v4.f32 [%0], {%1,%2,%3,%4};"
                             :: "l"(o), "f"(v[0]), "f"(v[1]), "f"(v[2]), "f"(v[3]) : "memory");
                asm volatile("red.global.add.v4.f32 [%0+16], {%1,%2,%3,%4};"
                             :: "l"(o), "f"(v[4]), "f"(v[5]), "f"(v[6]), "f"(v[7]) : "memory");
                asm volatile("red.global.add.v4.f32 [%0+32], {%1,%2,%3,%4};"
                             :: "l"(o), "f"(v[8]), "f"(v[9]), "f"(v[10]), "f"(v[11]) : "memory");
                asm volatile("red.global.add.v4.f32 [%0+48], {%1,%2,%3,%4};"
                             :: "l"(o), "f"(v[12]), "f"(v[13]), "f"(v[14]), "f"(v[15]) : "memory");
            }
        }
    }
}

// ---------- K2: per-channel sum / sumsq (MLP=4, channel fixed per thread) ----------
__global__ __launch_bounds__(256)
void k_stats(const float4* __restrict__ out4, int total4) {
    const int tid = threadIdx.x;
    const int cg  = (tid & 15) * 4;
    float s0 = 0.f, s1 = 0.f, s2 = 0.f, s3 = 0.f;
    float q0 = 0.f, q1 = 0.f, q2 = 0.f, q3 = 0.f;

    const int stride = gridDim.x * 256;
    int i = blockIdx.x * 256 + tid;
    for (; i + 3 * stride < total4; i += 4 * stride) {
        float4 v0 = out4[i];
        float4 v1 = out4[i + stride];
        float4 v2 = out4[i + 2 * stride];
        float4 v3 = out4[i + 3 * stride];
        s0 += v0.x + v1.x + v2.x + v3.x;
        s1 += v0.y + v1.y + v2.y + v3.y;
        s2 += v0.z + v1.z + v2.z + v3.z;
        s3 += v0.w + v1.w + v2.w + v3.w;
        q0 += v0.x*v0.x + v1.x*v1.x + v2.x*v2.x + v3.x*v3.x;
        q1 += v0.y*v0.y + v1.y*v1.y + v2.y*v2.y + v3.y*v3.y;
        q2 += v0.z*v0.z + v1.z*v1.z + v2.z*v2.z + v3.z*v3.z;
        q3 += v0.w*v0.w + v1.w*v1.w + v2.w*v2.w + v3.w*v3.w;
    }
    for (; i < total4; i += stride) {
        float4 v = out4[i];
        s0 += v.x; s1 += v.y; s2 += v.z; s3 += v.w;
        q0 += v.x*v.x; q1 += v.y*v.y; q2 += v.z*v.z; q3 += v.w*v.w;
    }

    __shared__ float ssum[OUTC];
    __shared__ float ssq[OUTC];
    if (tid < OUTC) { ssum[tid] = 0.f; ssq[tid] = 0.f; }
    __syncthreads();
    atomicAdd(&ssum[cg + 0], s0); atomicAdd(&ssq[cg + 0], q0);
    atomicAdd(&ssum[cg + 1], s1); atomicAdd(&ssq[cg + 1], q1);
    atomicAdd(&ssum[cg + 2], s2); atomicAdd(&ssq[cg + 2], q2);
    atomicAdd(&ssum[cg + 3], s3); atomicAdd(&ssq[cg + 3], q3);
    __syncthreads();
    if (tid < OUTC) {
        atomicAdd(&g_sum[tid],   ssum[tid]);
        atomicAdd(&g_sumsq[tid], ssq[tid]);
    }
}

// ---------- K3: BatchNorm + ReLU ----------
__global__ __launch_bounds__(256)
void k_bn(float4* __restrict__ out,
          const float* __restrict__ gamma, const float* __restrict__ beta,
          int total4, float invN)
{
    const int tid = threadIdx.x;
    const int cg  = (tid & 15) * 4;
    float mean[4], scl[4], bet[4];
    #pragma unroll
    for (int j = 0; j < 4; j++) {
        int c = cg + j;
        float m = g_sum[c] * invN;
        float var = g_sumsq[c] * invN - m * m;
        mean[j] = m;
        scl[j] = rsqrtf(var + BN_EPS) * gamma[c];
        bet[j] = beta[c];
    }
    const int stride = gridDim.x * 256;
    for (int i = blockIdx.x * 256 + tid; i < total4; i += stride) {
        float4 v = out[i];
        v.x = fmaxf((v.x - mean[0]) * scl[0] + bet[0], 0.f);
        v.y = fmaxf((v.y - mean[1]) * scl[1] + bet[1], 0.f);
        v.z = fmaxf((v.z - mean[2]) * scl[2] + bet[2], 0.f);
        v.w = fmaxf((v.w - mean[3]) * scl[3] + bet[3], 0.f);
        out[i] = v;
    }
}

// ---------- launch ----------
extern "C" void kernel_launch(void* const* d_in, const int* in_sizes, int n_in,
                              void* d_out, int out_size)
{
    const float* feats   = (const float*)d_in[0];
    const float* W       = (const float*)d_in[1];
    const float* gamma   = (const float*)d_in[2];
    const float* beta    = (const float*)d_in[3];
    const float* mask    = (const float*)d_in[4];
    const int*   in_idx  = (const int*)d_in[5];
    const int*   out_idx = (const int*)d_in[6];
    float*       out     = (float*)d_out;

    const int n = in_sizes[0] / INC;
    const int total4 = (n * OUTC) / 4;

    cudaFuncSetAttribute(k_gemm, cudaFuncAttributeMaxDynamicSharedMemorySize, SMEM_BYTES);

    k_init<<<1, 64>>>(mask, n);
    k_zero<<<2048, 256>>>((float4*)out, total4);

    dim3 grid((n + TILE_P - 1) / TILE_P, KOFF);
    k_gemm<<<grid, 256, SMEM_BYTES>>>(feats, W, in_idx, out_idx, out, n);

    k_stats<<<1184, 256>>>((const float4*)out, total4);
    k_bn<<<2048, 256>>>((float4*)out, gamma, beta, total4, 1.0f / (float)n);
}

// round 8
// speedup vs baseline: 1.8455x; 1.2517x over previous
#include <cuda_runtime.h>
#include <cuda_bf16.h>
#include <cstdint>

#define INC    64
#define OUTC   64
#define KOFF   27
#define TP     128
#define BN_EPS 1e-5f

__device__ int   g_counts[KOFF];
__device__ float g_sum[OUTC];
__device__ float g_sumsq[OUTC];

// ---------------- smem layout (byte offsets in dynamic smem) ----------------
#define SM_AHI   0
#define SM_ALO   16384
#define SM_BHI   32768
#define SM_BLO   40960
#define SMEM_TOTAL 49152
#define ACC_STRIDE 72      // floats per row in epilogue staging tile

#define SWZ128(x) ((x) ^ (((x) >> 3) & 0x70))

// ---------------- PTX helpers (base-target only: ldmatrix + mma.sync) ----------------
static __device__ __forceinline__ uint32_t smem_u32(const void* p) {
    uint32_t a;
    asm("{ .reg .u64 t; cvta.to.shared.u64 t, %1; cvt.u32.u64 %0, t; }" : "=r"(a) : "l"(p));
    return a;
}
static __device__ __forceinline__ void ldsm4(uint32_t* r, uint32_t addr) {
    asm volatile("ldmatrix.sync.aligned.m8n8.x4.shared.b16 {%0,%1,%2,%3}, [%4];"
                 : "=r"(r[0]), "=r"(r[1]), "=r"(r[2]), "=r"(r[3]) : "r"(addr));
}
static __device__ __forceinline__ void mma_bf16(float* c, const uint32_t* a,
                                                uint32_t b0, uint32_t b1) {
    asm volatile("mma.sync.aligned.m16n8k16.row.col.f32.bf16.bf16.f32 "
                 "{%0,%1,%2,%3}, {%4,%5,%6,%7}, {%8,%9}, {%0,%1,%2,%3};"
                 : "+f"(c[0]), "+f"(c[1]), "+f"(c[2]), "+f"(c[3])
                 : "r"(a[0]), "r"(a[1]), "r"(a[2]), "r"(a[3]), "r"(b0), "r"(b1));
}
static __device__ __forceinline__ void split_bf16(float x, unsigned short& h, unsigned short& l) {
    __nv_bfloat16 hb = __float2bfloat16_rn(x);
    float r = x - __bfloat162float(hb);
    __nv_bfloat16 lb = __float2bfloat16_rn(r);
    h = __bfloat16_as_ushort(hb);
    l = __bfloat16_as_ushort(lb);
}

// ---------- K0: counts + zero BN stats + zero output (fused) ----------
__global__ void k_prep(const float* __restrict__ mask, float4* __restrict__ out,
                       int n, int total4) {
    const int tid = threadIdx.x;
    if (blockIdx.x == 0) {
        if (tid < OUTC) { g_sum[tid] = 0.f; g_sumsq[tid] = 0.f; }
        if (tid < KOFF) {
            const float* m = mask + (size_t)tid * n;
            int lo = 0, hi = n;
            while (lo < hi) {
                int mid = (lo + hi) >> 1;
                if (m[mid] > 0.5f) lo = mid + 1; else hi = mid;
            }
            g_counts[tid] = lo;
        }
    }
    for (int i = blockIdx.x * blockDim.x + tid; i < total4; i += gridDim.x * blockDim.x)
        out[i] = make_float4(0.f, 0.f, 0.f, 0.f);
}

// ---------- K1: HMMA (mma.sync bf16, 3-pass hi/lo) scatter GEMM ----------
__global__ __launch_bounds__(256)
void k_gemm(const float* __restrict__ feats, const float* __restrict__ W,
            const int* __restrict__ in_idx, const int* __restrict__ out_idx,
            float* __restrict__ out, int n)
{
    extern __shared__ char smem[];
    const int k    = blockIdx.y;
    const int base = blockIdx.x * TP;
    const int cnt  = g_counts[k];
    if (base >= cnt) return;
    const int np = min(TP, cnt - base);

    const uint32_t sb = smem_u32(smem);
    const int tid = threadIdx.x, wid = tid >> 5, lane = tid & 31;
    const size_t kbase = (size_t)k * n + base;

    // --- gather A: 2 threads/pair, bf16 hi/lo split, SW128 rows (128B = 64 bf16) ---
    {
        const int p = tid >> 1;
        const int half = (tid & 1) * 32;
        char* ahi = smem + SM_AHI;
        char* alo = smem + SM_ALO;
        if (p < np) {
            const int src = in_idx[kbase + p];
            const float4* fr = (const float4*)(feats + (size_t)src * INC + half);
            #pragma unroll
            for (int j = 0; j < 8; j++) {
                float4 v = fr[j];
                unsigned short h0, h1, h2, h3, l0, l1, l2, l3;
                split_bf16(v.x, h0, l0); split_bf16(v.y, h1, l1);
                split_bf16(v.z, h2, l2); split_bf16(v.w, h3, l3);
                uint2 hv = make_uint2((uint32_t)h0 | ((uint32_t)h1 << 16),
                                      (uint32_t)h2 | ((uint32_t)h3 << 16));
                uint2 lv = make_uint2((uint32_t)l0 | ((uint32_t)l1 << 16),
                                      (uint32_t)l2 | ((uint32_t)l3 << 16));
                uint32_t off = SWZ128((uint32_t)(p * 128 + (half + j * 4) * 2));
                *(uint2*)(ahi + off) = hv;
                *(uint2*)(alo + off) = lv;
            }
        } else {
            #pragma unroll
            for (int j = 0; j < 8; j++) {
                uint32_t off = SWZ128((uint32_t)(p * 128 + (half + j * 4) * 2));
                *(uint2*)(smem + SM_AHI + off) = make_uint2(0u, 0u);
                *(uint2*)(smem + SM_ALO + off) = make_uint2(0u, 0u);
            }
        }
    }

    // --- stage B = W[k]^T as [outc c][inc kk], hi/lo split ---
    {
        const int c  = tid >> 2;
        const int kq = (tid & 3) * 16;
        const float* Wk = W + (size_t)k * INC * OUTC;
        #pragma unroll
        for (int j0 = 0; j0 < 16; j0 += 4) {
            float x0 = Wk[(size_t)(kq + j0 + 0) * OUTC + c];
            float x1 = Wk[(size_t)(kq + j0 + 1) * OUTC + c];
            float x2 = Wk[(size_t)(kq + j0 + 2) * OUTC + c];
            float x3 = Wk[(size_t)(kq + j0 + 3) * OUTC + c];
            unsigned short h0, h1, h2, h3, l0, l1, l2, l3;
            split_bf16(x0, h0, l0); split_bf16(x1, h1, l1);
            split_bf16(x2, h2, l2); split_bf16(x3, h3, l3);
            uint2 hv = make_uint2((uint32_t)h0 | ((uint32_t)h1 << 16),
                                  (uint32_t)h2 | ((uint32_t)h3 << 16));
            uint2 lv = make_uint2((uint32_t)l0 | ((uint32_t)l1 << 16),
                                  (uint32_t)l2 | ((uint32_t)l3 << 16));
            uint32_t off = SWZ128((uint32_t)(c * 128 + (kq + j0) * 2));
            *(uint2*)(smem + SM_BHI + off) = hv;
            *(uint2*)(smem + SM_BLO + off) = lv;
        }
    }
    __syncthreads();

    // --- compute: warp = 16 pairs x 64 cols; 3-pass hi/lo mma.sync ---
    const int pm = wid * 16;
    float acc[8][4];
    #pragma unroll
    for (int i = 0; i < 8; i++)
        #pragma unroll
        for (int j = 0; j < 4; j++) acc[i][j] = 0.f;

    const int lm = lane >> 3;                 // ldmatrix sub-matrix index
    const int lr = lane & 7;

    #pragma unroll
    for (int ks = 0; ks < 4; ks++) {
        // A fragments: m0 rows0-7/k0, m1 rows8-15/k0, m2 rows0-7/k8, m3 rows8-15/k8
        const int arow = pm + lr + (lm & 1) * 8;
        const int acol = ks * 16 + (lm >> 1) * 8;
        const uint32_t aoff = SWZ128((uint32_t)(arow * 128 + acol * 2));
        uint32_t ah[4], al[4];
        ldsm4(ah, sb + SM_AHI + aoff);
        ldsm4(al, sb + SM_ALO + aoff);

        #pragma unroll
        for (int nn = 0; nn < 4; nn++) {
            // B fragments: m0 n0-7/k0, m1 n0-7/k8, m2 n8-15/k0, m3 n8-15/k8
            const int brow = nn * 16 + lr + (lm >> 1) * 8;
            const int bcol = ks * 16 + (lm & 1) * 8;
            const uint32_t boff = SWZ128((uint32_t)(brow * 128 + bcol * 2));
            uint32_t bh[4], bl[4];
            ldsm4(bh, sb + SM_BHI + boff);
            ldsm4(bl, sb + SM_BLO + boff);

            mma_bf16(acc[2 * nn + 0], ah, bh[0], bh[1]);
            mma_bf16(acc[2 * nn + 1], ah, bh[2], bh[3]);
            mma_bf16(acc[2 * nn + 0], al, bh[0], bh[1]);
            mma_bf16(acc[2 * nn + 1], al, bh[2], bh[3]);
            mma_bf16(acc[2 * nn + 0], ah, bl[0], bl[1]);
            mma_bf16(acc[2 * nn + 1], ah, bl[2], bl[3]);
        }
    }
    __syncthreads();   // compute done; smem freed for Acc staging

    // --- stage fragments to Acc[128][72] (stride-72: conflict-free STS.64 phases) ---
    {
        float* Acc = (float*)smem;
        const int r0 = pm + (lane >> 2);
        const int c0 = (lane & 3) * 2;
        #pragma unroll
        for (int nn = 0; nn < 8; nn++) {
            const int col = nn * 8 + c0;
            *(float2*)&Acc[(size_t)r0 * ACC_STRIDE + col]       = make_float2(acc[nn][0], acc[nn][1]);
            *(float2*)&Acc[(size_t)(r0 + 8) * ACC_STRIDE + col] = make_float2(acc[nn][2], acc[nn][3]);
        }
    }
    __syncthreads();

    // --- scatter: 2 threads/row, 8 x red.global.add.v4 each ---
    {
        const float* Acc = (const float*)smem;
        const int row  = tid >> 1;
        const int half = (tid & 1) * 32;
        if (row < np) {
            const int dst = out_idx[kbase + row];
            float* o = out + (size_t)dst * OUTC + half;
            const float* a = &Acc[(size_t)row * ACC_STRIDE + half];
            #pragma unroll
            for (int j = 0; j < 8; j++) {
                float4 v = *(const float4*)(a + 4 * j);
                asm volatile("red.global.add.v4.f32 [%0], {%1,%2,%3,%4};"
                             :: "l"(o + 4 * j), "f"(v.x), "f"(v.y), "f"(v.z), "f"(v.w)
                             : "memory");
            }
        }
    }
}

// ---------- K2: per-channel sum / sumsq ----------
__global__ __launch_bounds__(256)
void k_stats(const float4* __restrict__ out4, int total4) {
    const int tid = threadIdx.x;
    const int cg  = (tid & 15) * 4;
    float s0 = 0.f, s1 = 0.f, s2 = 0.f, s3 = 0.f;
    float q0 = 0.f, q1 = 0.f, q2 = 0.f, q3 = 0.f;
    const int stride = gridDim.x * 256;
    int i = blockIdx.x * 256 + tid;
    for (; i + 3 * stride < total4; i += 4 * stride) {
        float4 v0 = out4[i];
        float4 v1 = out4[i + stride];
        float4 v2 = out4[i + 2 * stride];
        float4 v3 = out4[i + 3 * stride];
        s0 += v0.x + v1.x + v2.x + v3.x;
        s1 += v0.y + v1.y + v2.y + v3.y;
        s2 += v0.z + v1.z + v2.z + v3.z;
        s3 += v0.w + v1.w + v2.w + v3.w;
        q0 += v0.x*v0.x + v1.x*v1.x + v2.x*v2.x + v3.x*v3.x;
        q1 += v0.y*v0.y + v1.y*v1.y + v2.y*v2.y + v3.y*v3.y;
        q2 += v0.z*v0.z + v1.z*v1.z + v2.z*v2.z + v3.z*v3.z;
        q3 += v0.w*v0.w + v1.w*v1.w + v2.w*v2.w + v3.w*v3.w;
    }
    for (; i < total4; i += stride) {
        float4 v = out4[i];
        s0 += v.x; s1 += v.y; s2 += v.z; s3 += v.w;
        q0 += v.x*v.x; q1 += v.y*v.y; q2 += v.z*v.z; q3 += v.w*v.w;
    }
    __shared__ float ssum[OUTC];
    __shared__ float ssq[OUTC];
    if (tid < OUTC) { ssum[tid] = 0.f; ssq[tid] = 0.f; }
    __syncthreads();
    atomicAdd(&ssum[cg + 0], s0); atomicAdd(&ssq[cg + 0], q0);
    atomicAdd(&ssum[cg + 1], s1); atomicAdd(&ssq[cg + 1], q1);
    atomicAdd(&ssum[cg + 2], s2); atomicAdd(&ssq[cg + 2], q2);
    atomicAdd(&ssum[cg + 3], s3); atomicAdd(&ssq[cg + 3], q3);
    __syncthreads();
    if (tid < OUTC) {
        atomicAdd(&g_sum[tid],   ssum[tid]);
        atomicAdd(&g_sumsq[tid], ssq[tid]);
    }
}

// ---------- K3: BatchNorm + ReLU ----------
__global__ __launch_bounds__(256)
void k_bn(float4* __restrict__ out,
          const float* __restrict__ gamma, const float* __restrict__ beta,
          int total4, float invN)
{
    const int tid = threadIdx.x;
    const int cg  = (tid & 15) * 4;
    float mean[4], scl[4], bet[4];
    #pragma unroll
    for (int j = 0; j < 4; j++) {
        int c = cg + j;
        float m = g_sum[c] * invN;
        float var = g_sumsq[c] * invN - m * m;
        mean[j] = m;
        scl[j] = rsqrtf(var + BN_EPS) * gamma[c];
        bet[j] = beta[c];
    }
    const int stride = gridDim.x * 256;
    for (int i = blockIdx.x * 256 + tid; i < total4; i += stride) {
        float4 v = out[i];
        v.x = fmaxf((v.x - mean[0]) * scl[0] + bet[0], 0.f);
        v.y = fmaxf((v.y - mean[1]) * scl[1] + bet[1], 0.f);
        v.z = fmaxf((v.z - mean[2]) * scl[2] + bet[2], 0.f);
        v.w = fmaxf((v.w - mean[3]) * scl[3] + bet[3], 0.f);
        out[i] = v;
    }
}

// ---------- launch ----------
extern "C" void kernel_launch(void* const* d_in, const int* in_sizes, int n_in,
                              void* d_out, int out_size)
{
    const float* feats   = (const float*)d_in[0];
    const float* W       = (const float*)d_in[1];
    const float* gamma   = (const float*)d_in[2];
    const float* beta    = (const float*)d_in[3];
    const float* mask    = (const float*)d_in[4];
    const int*   in_idx  = (const int*)d_in[5];
    const int*   out_idx = (const int*)d_in[6];
    float*       out     = (float*)d_out;

    const int n = in_sizes[0] / INC;
    const int total4 = (n * OUTC) / 4;

    cudaFuncSetAttribute(k_gemm, cudaFuncAttributeMaxDynamicSharedMemorySize, SMEM_TOTAL);

    k_prep<<<2048, 256>>>(mask, (float4*)out, n, total4);

    dim3 grid((n + TP - 1) / TP, KOFF);
    k_gemm<<<grid, 256, SMEM_TOTAL>>>(feats, W, in_idx, out_idx, out, n);

    k_stats<<<1184, 256>>>((const float4*)out, total4);
    k_bn<<<2048, 256>>>((float4*)out, gamma, beta, total4, 1.0f / (float)n);
}

// round 9
// speedup vs baseline: 1.8942x; 1.0264x over previous
#include <cuda_runtime.h>
#include <cuda_bf16.h>
#include <cstdint>

#define INC    64
#define OUTC   64
#define KOFF   27
#define TP     256
#define NMAX   400000
#define BN_EPS 1e-5f

__device__ int   g_counts[KOFF];
__device__ float g_sum[OUTC];
__device__ float g_sumsq[OUTC];

// precomputed bf16 hi/lo operands
__device__ uint4 FHI4[NMAX * 8];            // feats hi: [row][128B]
__device__ uint4 FLO4[NMAX * 8];            // feats lo
__device__ uint4 WHI4[KOFF * 512];          // W^T hi, SW128-swizzled B tiles (8KB each)
__device__ uint4 WLO4[KOFF * 512];

// ---------------- smem layout ----------------
#define SM_AHI   0
#define SM_ALO   32768
#define SM_BHI   65536
#define SM_BLO   73728
#define SMEM_TOTAL 81920
#define ACC_STRIDE 72

#define SWZ128(x) ((x) ^ (((x) >> 3) & 0x70))

static __device__ __forceinline__ uint32_t smem_u32(const void* p) {
    uint32_t a;
    asm("{ .reg .u64 t; cvta.to.shared.u64 t, %1; cvt.u32.u64 %0, t; }" : "=r"(a) : "l"(p));
    return a;
}
static __device__ __forceinline__ void ldsm4(uint32_t* r, uint32_t addr) {
    asm volatile("ldmatrix.sync.aligned.m8n8.x4.shared.b16 {%0,%1,%2,%3}, [%4];"
                 : "=r"(r[0]), "=r"(r[1]), "=r"(r[2]), "=r"(r[3]) : "r"(addr));
}
static __device__ __forceinline__ void mma_bf16(float* c, const uint32_t* a,
                                                uint32_t b0, uint32_t b1) {
    asm volatile("mma.sync.aligned.m16n8k16.row.col.f32.bf16.bf16.f32 "
                 "{%0,%1,%2,%3}, {%4,%5,%6,%7}, {%8,%9}, {%0,%1,%2,%3};"
                 : "+f"(c[0]), "+f"(c[1]), "+f"(c[2]), "+f"(c[3])
                 : "r"(a[0]), "r"(a[1]), "r"(a[2]), "r"(a[3]), "r"(b0), "r"(b1));
}
static __device__ __forceinline__ void split_bf16(float x, unsigned short& h, unsigned short& l) {
    __nv_bfloat16 hb = __float2bfloat16_rn(x);
    float r = x - __bfloat162float(hb);
    __nv_bfloat16 lb = __float2bfloat16_rn(r);
    h = __bfloat16_as_ushort(hb);
    l = __bfloat16_as_ushort(lb);
}

// ---------- K0: counts + zero BN stats + zero output ----------
__global__ void k_prep(const float* __restrict__ mask, float4* __restrict__ out,
                       int n, int total4) {
    const int tid = threadIdx.x;
    if (blockIdx.x == 0) {
        if (tid < OUTC) { g_sum[tid] = 0.f; g_sumsq[tid] = 0.f; }
        if (tid < KOFF) {
            const float* m = mask + (size_t)tid * n;
            int lo = 0, hi = n;
            while (lo < hi) {
                int mid = (lo + hi) >> 1;
                if (m[mid] > 0.5f) lo = mid + 1; else hi = mid;
            }
            g_counts[tid] = lo;
        }
    }
    for (int i = blockIdx.x * blockDim.x + tid; i < total4; i += gridDim.x * blockDim.x)
        out[i] = make_float4(0.f, 0.f, 0.f, 0.f);
}

// ---------- K0b: feats -> bf16 hi/lo (one streaming pass) ----------
__global__ void k_conv_feats(const float4* __restrict__ feats4, int nf4) {
    uint2* fh = (uint2*)FHI4;
    uint2* fl = (uint2*)FLO4;
    for (int i = blockIdx.x * blockDim.x + threadIdx.x; i < nf4;
         i += gridDim.x * blockDim.x) {
        float4 v = feats4[i];
        unsigned short h0, h1, h2, h3, l0, l1, l2, l3;
        split_bf16(v.x, h0, l0); split_bf16(v.y, h1, l1);
        split_bf16(v.z, h2, l2); split_bf16(v.w, h3, l3);
        fh[i] = make_uint2((uint32_t)h0 | ((uint32_t)h1 << 16),
                           (uint32_t)h2 | ((uint32_t)h3 << 16));
        fl[i] = make_uint2((uint32_t)l0 | ((uint32_t)l1 << 16),
                           (uint32_t)l2 | ((uint32_t)l3 << 16));
    }
}

// ---------- K0c: W -> transposed, hi/lo, SW128-swizzled B tiles ----------
__global__ void k_conv_w(const float* __restrict__ W) {
    const int k   = blockIdx.x;
    const int tid = threadIdx.x;
    const int c   = tid >> 2;
    const int kq  = (tid & 3) * 16;
    const float* Wk = W + (size_t)k * INC * OUTC;
    char* wh = (char*)(WHI4 + k * 512);
    char* wl = (char*)(WLO4 + k * 512);
    #pragma unroll
    for (int j0 = 0; j0 < 16; j0 += 4) {
        float x0 = Wk[(size_t)(kq + j0 + 0) * OUTC + c];
        float x1 = Wk[(size_t)(kq + j0 + 1) * OUTC + c];
        float x2 = Wk[(size_t)(kq + j0 + 2) * OUTC + c];
        float x3 = Wk[(size_t)(kq + j0 + 3) * OUTC + c];
        unsigned short h0, h1, h2, h3, l0, l1, l2, l3;
        split_bf16(x0, h0, l0); split_bf16(x1, h1, l1);
        split_bf16(x2, h2, l2); split_bf16(x3, h3, l3);
        uint32_t off = SWZ128((uint32_t)(c * 128 + (kq + j0) * 2));
        *(uint2*)(wh + off) = make_uint2((uint32_t)h0 | ((uint32_t)h1 << 16),
                                         (uint32_t)h2 | ((uint32_t)h3 << 16));
        *(uint2*)(wl + off) = make_uint2((uint32_t)l0 | ((uint32_t)l1 << 16),
                                         (uint32_t)l2 | ((uint32_t)l3 << 16));
    }
}

// ---------- K1: HMMA scatter GEMM (M=256 tiles, no in-kernel conversion) ----------
__global__ __launch_bounds__(256)
void k_gemm(const int* __restrict__ in_idx, const int* __restrict__ out_idx,
            float* __restrict__ out, int n)
{
    extern __shared__ char smem[];
    const int k    = blockIdx.y;
    const int base = blockIdx.x * TP;
    const int cnt  = g_counts[k];
    if (base >= cnt) return;
    const int np = min(TP, cnt - base);

    const uint32_t sb = smem_u32(smem);
    const int tid = threadIdx.x, wid = tid >> 5, lane = tid & 31;
    const size_t kbase = (size_t)k * n + base;

    // --- copy pre-swizzled B tiles (8KB hi + 8KB lo) ---
    {
        const uint4* wh = WHI4 + k * 512;
        const uint4* wl = WLO4 + k * 512;
        uint4* bh = (uint4*)(smem + SM_BHI);
        uint4* bl = (uint4*)(smem + SM_BLO);
        bh[tid]       = wh[tid];
        bh[tid + 256] = wh[tid + 256];
        bl[tid]       = wl[tid];
        bl[tid + 256] = wl[tid + 256];
    }

    // --- gather A: 1 thread/pair, bf16 rows direct from FHI/FLO (no cvt) ---
    // rows >= np left uninitialized: their outputs are never scattered.
    {
        const int p = tid;
        if (p < np) {
            const int src = in_idx[kbase + p];
            const uint4* fh = FHI4 + (size_t)src * 8;
            const uint4* fl = FLO4 + (size_t)src * 8;
            #pragma unroll
            for (int j = 0; j < 8; j++) {
                uint32_t off = SWZ128((uint32_t)(p * 128 + j * 16));
                *(uint4*)(smem + SM_AHI + off) = fh[j];
                *(uint4*)(smem + SM_ALO + off) = fl[j];
            }
        }
    }
    __syncthreads();

    // --- compute: warp = 32 pairs x 64 cols; 3-pass hi/lo mma.sync ---
    const int pm = wid * 32;
    float acc[2][8][4];
    #pragma unroll
    for (int mb = 0; mb < 2; mb++)
        #pragma unroll
        for (int i = 0; i < 8; i++)
            #pragma unroll
            for (int j = 0; j < 4; j++) acc[mb][i][j] = 0.f;

    const int lm = lane >> 3;
    const int lr = lane & 7;

    #pragma unroll
    for (int ks = 0; ks < 4; ks++) {
        uint32_t ah[2][4], al[2][4];
        #pragma unroll
        for (int mb = 0; mb < 2; mb++) {
            const int arow = pm + mb * 16 + lr + (lm & 1) * 8;
            const int acol = ks * 16 + (lm >> 1) * 8;
            const uint32_t aoff = SWZ128((uint32_t)(arow * 128 + acol * 2));
            ldsm4(ah[mb], sb + SM_AHI + aoff);
            ldsm4(al[mb], sb + SM_ALO + aoff);
        }
        #pragma unroll
        for (int nn = 0; nn < 4; nn++) {
            const int brow = nn * 16 + lr + (lm >> 1) * 8;
            const int bcol = ks * 16 + (lm & 1) * 8;
            const uint32_t boff = SWZ128((uint32_t)(brow * 128 + bcol * 2));
            uint32_t bh[4], bl[4];
            ldsm4(bh, sb + SM_BHI + boff);
            ldsm4(bl, sb + SM_BLO + boff);
            #pragma unroll
            for (int mb = 0; mb < 2; mb++) {
                mma_bf16(acc[mb][2 * nn + 0], ah[mb], bh[0], bh[1]);
                mma_bf16(acc[mb][2 * nn + 1], ah[mb], bh[2], bh[3]);
                mma_bf16(acc[mb][2 * nn + 0], al[mb], bh[0], bh[1]);
                mma_bf16(acc[mb][2 * nn + 1], al[mb], bh[2], bh[3]);
                mma_bf16(acc[mb][2 * nn + 0], ah[mb], bl[0], bl[1]);
                mma_bf16(acc[mb][2 * nn + 1], ah[mb], bl[2], bl[3]);
            }
        }
    }
    __syncthreads();

    // --- stage fragments to Acc[256][72] ---
    {
        float* Acc = (float*)smem;
        #pragma unroll
        for (int mb = 0; mb < 2; mb++) {
            const int r0 = pm + mb * 16 + (lane >> 2);
            const int c0 = (lane & 3) * 2;
            #pragma unroll
            for (int nn = 0; nn < 8; nn++) {
                const int col = nn * 8 + c0;
                *(float2*)&Acc[(size_t)r0 * ACC_STRIDE + col] =
                    make_float2(acc[mb][nn][0], acc[mb][nn][1]);
                *(float2*)&Acc[(size_t)(r0 + 8) * ACC_STRIDE + col] =
                    make_float2(acc[mb][nn][2], acc[mb][nn][3]);
            }
        }
    }
    __syncthreads();

    // --- scatter: 1 thread/row, 16 x red.global.add.v4 ---
    {
        const float* Acc = (const float*)smem;
        const int row = tid;
        if (row < np) {
            const int dst = out_idx[kbase + row];
            float* o = out + (size_t)dst * OUTC;
            const float* a = &Acc[(size_t)row * ACC_STRIDE];
            #pragma unroll
            for (int j = 0; j < 16; j++) {
                float4 v = *(const float4*)(a + 4 * j);
                asm volatile("red.global.add.v4.f32 [%0], {%1,%2,%3,%4};"
                             :: "l"(o + 4 * j), "f"(v.x), "f"(v.y), "f"(v.z), "f"(v.w)
                             : "memory");
            }
        }
    }
}

// ---------- K2: per-channel sum / sumsq ----------
__global__ __launch_bounds__(256)
void k_stats(const float4* __restrict__ out4, int total4) {
    const int tid = threadIdx.x;
    const int cg  = (tid & 15) * 4;
    float s0 = 0.f, s1 = 0.f, s2 = 0.f, s3 = 0.f;
    float q0 = 0.f, q1 = 0.f, q2 = 0.f, q3 = 0.f;
    const int stride = gridDim.x * 256;
    int i = blockIdx.x * 256 + tid;
    for (; i + 3 * stride < total4; i += 4 * stride) {
        float4 v0 = out4[i];
        float4 v1 = out4[i + stride];
        float4 v2 = out4[i + 2 * stride];
        float4 v3 = out4[i + 3 * stride];
        s0 += v0.x + v1.x + v2.x + v3.x;
        s1 += v0.y + v1.y + v2.y + v3.y;
        s2 += v0.z + v1.z + v2.z + v3.z;
        s3 += v0.w + v1.w + v2.w + v3.w;
        q0 += v0.x*v0.x + v1.x*v1.x + v2.x*v2.x + v3.x*v3.x;
        q1 += v0.y*v0.y + v1.y*v1.y + v2.y*v2.y + v3.y*v3.y;
        q2 += v0.z*v0.z + v1.z*v1.z + v2.z*v2.z + v3.z*v3.z;
        q3 += v0.w*v0.w + v1.w*v1.w + v2.w*v2.w + v3.w*v3.w;
    }
    for (; i < total4; i += stride) {
        float4 v = out4[i];
        s0 += v.x; s1 += v.y; s2 += v.z; s3 += v.w;
        q0 += v.x*v.x; q1 += v.y*v.y; q2 += v.z*v.z; q3 += v.w*v.w;
    }
    __shared__ float ssum[OUTC];
    __shared__ float ssq[OUTC];
    if (tid < OUTC) { ssum[tid] = 0.f; ssq[tid] = 0.f; }
    __syncthreads();
    atomicAdd(&ssum[cg + 0], s0); atomicAdd(&ssq[cg + 0], q0);
    atomicAdd(&ssum[cg + 1], s1); atomicAdd(&ssq[cg + 1], q1);
    atomicAdd(&ssum[cg + 2], s2); atomicAdd(&ssq[cg + 2], q2);
    atomicAdd(&ssum[cg + 3], s3); atomicAdd(&ssq[cg + 3], q3);
    __syncthreads();
    if (tid < OUTC) {
        atomicAdd(&g_sum[tid],   ssum[tid]);
        atomicAdd(&g_sumsq[tid], ssq[tid]);
    }
}

// ---------- K3: BatchNorm + ReLU ----------
__global__ __launch_bounds__(256)
void k_bn(float4* __restrict__ out,
          const float* __restrict__ gamma, const float* __restrict__ beta,
          int total4, float invN)
{
    const int tid = threadIdx.x;
    const int cg  = (tid & 15) * 4;
    float mean[4], scl[4], bet[4];
    #pragma unroll
    for (int j = 0; j < 4; j++) {
        int c = cg + j;
        float m = g_sum[c] * invN;
        float var = g_sumsq[c] * invN - m * m;
        mean[j] = m;
        scl[j] = rsqrtf(var + BN_EPS) * gamma[c];
        bet[j] = beta[c];
    }
    const int stride = gridDim.x * 256;
    for (int i = blockIdx.x * 256 + tid; i < total4; i += stride) {
        float4 v = out[i];
        v.x = fmaxf((v.x - mean[0]) * scl[0] + bet[0], 0.f);
        v.y = fmaxf((v.y - mean[1]) * scl[1] + bet[1], 0.f);
        v.z = fmaxf((v.z - mean[2]) * scl[2] + bet[2], 0.f);
        v.w = fmaxf((v.w - mean[3]) * scl[3] + bet[3], 0.f);
        out[i] = v;
    }
}

// ---------- launch ----------
extern "C" void kernel_launch(void* const* d_in, const int* in_sizes, int n_in,
                              void* d_out, int out_size)
{
    const float* feats   = (const float*)d_in[0];
    const float* W       = (const float*)d_in[1];
    const float* gamma   = (const float*)d_in[2];
    const float* beta    = (const float*)d_in[3];
    const float* mask    = (const float*)d_in[4];
    const int*   in_idx  = (const int*)d_in[5];
    const int*   out_idx = (const int*)d_in[6];
    float*       out     = (float*)d_out;

    const int n = in_sizes[0] / INC;
    const int total4 = (n * OUTC) / 4;

    cudaFuncSetAttribute(k_gemm, cudaFuncAttributeMaxDynamicSharedMemorySize, SMEM_TOTAL);

    k_prep<<<2048, 256>>>(mask, (float4*)out, n, total4);
    k_conv_feats<<<2048, 256>>>((const float4*)feats, n * 16);
    k_conv_w<<<KOFF, 256>>>(W);

    dim3 grid((n + TP - 1) / TP, KOFF);
    k_gemm<<<grid, 256, SMEM_TOTAL>>>(in_idx, out_idx, out, n);

    k_stats<<<1184, 256>>>((const float4*)out, total4);
    k_bn<<<2048, 256>>>((float4*)out, gamma, beta, total4, 1.0f / (float)n);
}

// round 11
// speedup vs baseline: 2.3549x; 1.2432x over previous
#include <cuda_runtime.h>
#include <cuda_bf16.h>
#include <cstdint>

#define INC    64
#define OUTC   64
#define KOFF   27
#define TP     256
#define NMAX   400000
#define BN_EPS 1e-5f

__device__ int   g_counts[KOFF];
__device__ float g_sum[OUTC];
__device__ float g_sumsq[OUTC];

// precomputed bf16 hi/lo operands
__device__ uint4 FHI4[NMAX * 8];            // feats hi: [row][128B]
__device__ uint4 FLO4[NMAX * 8];            // feats lo
__device__ uint4 WHI4[KOFF * 512];          // W^T hi, SW128-swizzled B tiles (8KB each)
__device__ uint4 WLO4[KOFF * 512];

// ---------------- smem layout ----------------
#define SM_AHI   0
#define SM_ALO   32768
#define SM_BHI   65536
#define SM_BLO   73728
#define SM_DL    81920
#define SMEM_TOTAL (81920 + TP * 4)

#define SWZ128(x) ((x) ^ (((x) >> 3) & 0x70))

static __device__ __forceinline__ uint32_t smem_u32(const void* p) {
    uint32_t a;
    asm("{ .reg .u64 t; cvta.to.shared.u64 t, %1; cvt.u32.u64 %0, t; }" : "=r"(a) : "l"(p));
    return a;
}
static __device__ __forceinline__ void cpasync16(uint32_t dst, const void* src) {
    asm volatile("cp.async.cg.shared.global [%0], [%1], 16;" :: "r"(dst), "l"(src) : "memory");
}
static __device__ __forceinline__ void ldsm4(uint32_t* r, uint32_t addr) {
    asm volatile("ldmatrix.sync.aligned.m8n8.x4.shared.b16 {%0,%1,%2,%3}, [%4];"
                 : "=r"(r[0]), "=r"(r[1]), "=r"(r[2]), "=r"(r[3]) : "r"(addr));
}
static __device__ __forceinline__ void mma_bf16(float* c, const uint32_t* a,
                                                uint32_t b0, uint32_t b1) {
    asm volatile("mma.sync.aligned.m16n8k16.row.col.f32.bf16.bf16.f32 "
                 "{%0,%1,%2,%3}, {%4,%5,%6,%7}, {%8,%9}, {%0,%1,%2,%3};"
                 : "+f"(c[0]), "+f"(c[1]), "+f"(c[2]), "+f"(c[3])
                 : "r"(a[0]), "r"(a[1]), "r"(a[2]), "r"(a[3]), "r"(b0), "r"(b1));
}
static __device__ __forceinline__ void split_bf16(float x, unsigned short& h, unsigned short& l) {
    __nv_bfloat16 hb = __float2bfloat16_rn(x);
    float r = x - __bfloat162float(hb);
    __nv_bfloat16 lb = __float2bfloat16_rn(r);
    h = __bfloat16_as_ushort(hb);
    l = __bfloat16_as_ushort(lb);
}

// ---------- K0: counts + zero BN stats + zero output + feats hi/lo split ----------
__global__ void k_prep(const float* __restrict__ mask, float4* __restrict__ out,
                       const float4* __restrict__ feats4, int n, int total4) {
    const int tid = threadIdx.x;
    if (blockIdx.x == 0) {
        if (tid < OUTC) { g_sum[tid] = 0.f; g_sumsq[tid] = 0.f; }
        if (tid < KOFF) {
            const float* m = mask + (size_t)tid * n;
            int lo = 0, hi = n;
            while (lo < hi) {
                int mid = (lo + hi) >> 1;
                if (m[mid] > 0.5f) lo = mid + 1; else hi = mid;
            }
            g_counts[tid] = lo;
        }
    }
    const int gstride = gridDim.x * blockDim.x;
    for (int i = blockIdx.x * blockDim.x + tid; i < total4; i += gstride)
        out[i] = make_float4(0.f, 0.f, 0.f, 0.f);

    uint2* fh = (uint2*)FHI4;
    uint2* fl = (uint2*)FLO4;
    const int nf4 = n * 16;
    for (int i = blockIdx.x * blockDim.x + tid; i < nf4; i += gstride) {
        float4 v = feats4[i];
        unsigned short h0, h1, h2, h3, l0, l1, l2, l3;
        split_bf16(v.x, h0, l0); split_bf16(v.y, h1, l1);
        split_bf16(v.z, h2, l2); split_bf16(v.w, h3, l3);
        fh[i] = make_uint2((uint32_t)h0 | ((uint32_t)h1 << 16),
                           (uint32_t)h2 | ((uint32_t)h3 << 16));
        fl[i] = make_uint2((uint32_t)l0 | ((uint32_t)l1 << 16),
                           (uint32_t)l2 | ((uint32_t)l3 << 16));
    }
}

// ---------- K0c: W -> transposed, hi/lo, SW128-swizzled B tiles ----------
__global__ void k_conv_w(const float* __restrict__ W) {
    const int k   = blockIdx.x;
    const int tid = threadIdx.x;
    const int c   = tid >> 2;
    const int kq  = (tid & 3) * 16;
    const float* Wk = W + (size_t)k * INC * OUTC;
    char* wh = (char*)(WHI4 + k * 512);
    char* wl = (char*)(WLO4 + k * 512);
    #pragma unroll
    for (int j0 = 0; j0 < 16; j0 += 4) {
        float x0 = Wk[(size_t)(kq + j0 + 0) * OUTC + c];
        float x1 = Wk[(size_t)(kq + j0 + 1) * OUTC + c];
        float x2 = Wk[(size_t)(kq + j0 + 2) * OUTC + c];
        float x3 = Wk[(size_t)(kq + j0 + 3) * OUTC + c];
        unsigned short h0, h1, h2, h3, l0, l1, l2, l3;
        split_bf16(x0, h0, l0); split_bf16(x1, h1, l1);
        split_bf16(x2, h2, l2); split_bf16(x3, h3, l3);
        uint32_t off = SWZ128((uint32_t)(c * 128 + (kq + j0) * 2));
        *(uint2*)(wh + off) = make_uint2((uint32_t)h0 | ((uint32_t)h1 << 16),
                                         (uint32_t)h2 | ((uint32_t)h3 << 16));
        *(uint2*)(wl + off) = make_uint2((uint32_t)l0 | ((uint32_t)l1 << 16),
                                         (uint32_t)l2 | ((uint32_t)l3 << 16));
    }
}

// ---------- K1: HMMA scatter GEMM (cp.async gather, direct register scatter) ----------
__global__ __launch_bounds__(256)
void k_gemm(const int* __restrict__ in_idx, const int* __restrict__ out_idx,
            float* __restrict__ out, int n)
{
    extern __shared__ char smem[];
    const int k    = blockIdx.y;
    const int base = blockIdx.x * TP;
    const int cnt  = g_counts[k];
    if (base >= cnt) return;
    const int np = min(TP, cnt - base);

    const uint32_t sb = smem_u32(smem);
    const int tid = threadIdx.x, wid = tid >> 5, lane = tid & 31;
    const size_t kbase = (size_t)k * n + base;
    int* dl = (int*)(smem + SM_DL);

    // --- B tiles via cp.async (8KB hi + 8KB lo, pre-swizzled) ---
    {
        const uint4* wh = WHI4 + k * 512;
        const uint4* wl = WLO4 + k * 512;
        cpasync16(sb + SM_BHI + tid * 16,         wh + tid);
        cpasync16(sb + SM_BHI + (tid + 256) * 16, wh + tid + 256);
        cpasync16(sb + SM_BLO + tid * 16,         wl + tid);
        cpasync16(sb + SM_BLO + (tid + 256) * 16, wl + tid + 256);
    }

    // --- gather A via cp.async: 1 thread/pair; rows >= np stay garbage (never scattered) ---
    {
        const int p = tid;
        if (p < np) {
            const int src = in_idx[kbase + p];
            dl[p] = out_idx[kbase + p];
            const uint4* fh = FHI4 + (size_t)src * 8;
            const uint4* fl = FLO4 + (size_t)src * 8;
            #pragma unroll
            for (int j = 0; j < 8; j++) {
                uint32_t off = SWZ128((uint32_t)(p * 128 + j * 16));
                cpasync16(sb + SM_AHI + off, fh + j);
                cpasync16(sb + SM_ALO + off, fl + j);
            }
        }
    }
    asm volatile("cp.async.commit_group;" ::: "memory");
    asm volatile("cp.async.wait_group 0;" ::: "memory");
    __syncthreads();

    // --- compute: warp = 32 pairs x 64 cols; 3-pass hi/lo mma.sync ---
    const int pm = wid * 32;
    float acc[2][8][4];
    #pragma unroll
    for (int mb = 0; mb < 2; mb++)
        #pragma unroll
        for (int i = 0; i < 8; i++)
            #pragma unroll
            for (int j = 0; j < 4; j++) acc[mb][i][j] = 0.f;

    const int lm = lane >> 3;
    const int lr = lane & 7;

    #pragma unroll
    for (int ks = 0; ks < 4; ks++) {
        uint32_t ah[2][4], al[2][4];
        #pragma unroll
        for (int mb = 0; mb < 2; mb++) {
            const int arow = pm + mb * 16 + lr + (lm & 1) * 8;
            const int acol = ks * 16 + (lm >> 1) * 8;
            const uint32_t aoff = SWZ128((uint32_t)(arow * 128 + acol * 2));
            ldsm4(ah[mb], sb + SM_AHI + aoff);
            ldsm4(al[mb], sb + SM_ALO + aoff);
        }
        #pragma unroll
        for (int nn = 0; nn < 4; nn++) {
            const int brow = nn * 16 + lr + (lm >> 1) * 8;
            const int bcol = ks * 16 + (lm & 1) * 8;
            const uint32_t boff = SWZ128((uint32_t)(brow * 128 + bcol * 2));
            uint32_t bh[4], bl[4];
            ldsm4(bh, sb + SM_BHI + boff);
            ldsm4(bl, sb + SM_BLO + boff);
            #pragma unroll
            for (int mb = 0; mb < 2; mb++) {
                mma_bf16(acc[mb][2 * nn + 0], ah[mb], bh[0], bh[1]);
                mma_bf16(acc[mb][2 * nn + 1], ah[mb], bh[2], bh[3]);
                mma_bf16(acc[mb][2 * nn + 0], al[mb], bh[0], bh[1]);
                mma_bf16(acc[mb][2 * nn + 1], al[mb], bh[2], bh[3]);
                mma_bf16(acc[mb][2 * nn + 0], ah[mb], bl[0], bl[1]);
                mma_bf16(acc[mb][2 * nn + 1], ah[mb], bl[2], bl[3]);
            }
        }
    }

    // --- direct register scatter: red.v2 per fragment pair (no staging) ---
    {
        const int colb = (lane & 3) * 2;
        #pragma unroll
        for (int mb = 0; mb < 2; mb++) {
            const int r0 = pm + mb * 16 + (lane >> 2);
            #pragma unroll
            for (int half = 0; half < 2; half++) {
                const int r = r0 + half * 8;
                if (r < np) {
                    const int dst = dl[r];
                    float* o = out + (size_t)dst * OUTC;
                    #pragma unroll
                    for (int j = 0; j < 8; j++) {
                        const int col = (j >> 1) * 16 + (j & 1) * 8 + colb;
                        asm volatile("red.global.add.v2.f32 [%0], {%1,%2};"
                                     :: "l"(o + col),
                                        "f"(acc[mb][j][2 * half]),
                                        "f"(acc[mb][j][2 * half + 1]) : "memory");
                    }
                }
            }
        }
    }
}

// ---------- K2: per-channel sum / sumsq ----------
__global__ __launch_bounds__(256)
void k_stats(const float4* __restrict__ out4, int total4) {
    const int tid = threadIdx.x;
    const int cg  = (tid & 15) * 4;
    float s0 = 0.f, s1 = 0.f, s2 = 0.f, s3 = 0.f;
    float q0 = 0.f, q1 = 0.f, q2 = 0.f, q3 = 0.f;
    const int stride = gridDim.x * 256;
    int i = blockIdx.x * 256 + tid;
    for (; i + 3 * stride < total4; i += 4 * stride) {
        float4 v0 = out4[i];
        float4 v1 = out4[i + stride];
        float4 v2 = out4[i + 2 * stride];
        float4 v3 = out4[i + 3 * stride];
        s0 += v0.x + v1.x + v2.x + v3.x;
        s1 += v0.y + v1.y + v2.y + v3.y;
        s2 += v0.z + v1.z + v2.z + v3.z;
        s3 += v0.w + v1.w + v2.w + v3.w;
        q0 += v0.x*v0.x + v1.x*v1.x + v2.x*v2.x + v3.x*v3.x;
        q1 += v0.y*v0.y + v1.y*v1.y + v2.y*v2.y + v3.y*v3.y;
        q2 += v0.z*v0.z + v1.z*v1.z + v2.z*v2.z + v3.z*v3.z;
        q3 += v0.w*v0.w + v1.w*v1.w + v2.w*v2.w + v3.w*v3.w;
    }
    for (; i < total4; i += stride) {
        float4 v = out4[i];
        s0 += v.x; s1 += v.y; s2 += v.z; s3 += v.w;
        q0 += v.x*v.x; q1 += v.y*v.y; q2 += v.z*v.z; q3 += v.w*v.w;
    }
    __shared__ float ssum[OUTC];
    __shared__ float ssq[OUTC];
    if (tid < OUTC) { ssum[tid] = 0.f; ssq[tid] = 0.f; }
    __syncthreads();
    atomicAdd(&ssum[cg + 0], s0); atomicAdd(&ssq[cg + 0], q0);
    atomicAdd(&ssum[cg + 1], s1); atomicAdd(&ssq[cg + 1], q1);
    atomicAdd(&ssum[cg + 2], s2); atomicAdd(&ssq[cg + 2], q2);
    atomicAdd(&ssum[cg + 3], s3); atomicAdd(&ssq[cg + 3], q3);
    __syncthreads();
    if (tid < OUTC) {
        atomicAdd(&g_sum[tid],   ssum[tid]);
        atomicAdd(&g_sumsq[tid], ssq[tid]);
    }
}

// ---------- K3: BatchNorm + ReLU ----------
__global__ __launch_bounds__(256)
void k_bn(float4* __restrict__ out,
          const float* __restrict__ gamma, const float* __restrict__ beta,
          int total4, float invN)
{
    const int tid = threadIdx.x;
    const int cg  = (tid & 15) * 4;
    float mean[4], scl[4], bet[4];
    #pragma unroll
    for (int j = 0; j < 4; j++) {
        int c = cg + j;
        float m = g_sum[c] * invN;
        float var = g_sumsq[c] * invN - m * m;
        mean[j] = m;
        scl[j] = rsqrtf(var + BN_EPS) * gamma[c];
        bet[j] = beta[c];
    }
    const int stride = gridDim.x * 256;
    for (int i = blockIdx.x * 256 + tid; i < total4; i += stride) {
        float4 v = out[i];
        v.x = fmaxf((v.x - mean[0]) * scl[0] + bet[0], 0.f);
        v.y = fmaxf((v.y - mean[1]) * scl[1] + bet[1], 0.f);
        v.z = fmaxf((v.z - mean[2]) * scl[2] + bet[2], 0.f);
        v.w = fmaxf((v.w - mean[3]) * scl[3] + bet[3], 0.f);
        out[i] = v;
    }
}

// ---------- launch ----------
extern "C" void kernel_launch(void* const* d_in, const int* in_sizes, int n_in,
                              void* d_out, int out_size)
{
    const float* feats   = (const float*)d_in[0];
    const float* W       = (const float*)d_in[1];
    const float* gamma   = (const float*)d_in[2];
    const float* beta    = (const float*)d_in[3];
    const float* mask    = (const float*)d_in[4];
    const int*   in_idx  = (const int*)d_in[5];
    const int*   out_idx = (const int*)d_in[6];
    float*       out     = (float*)d_out;

    const int n = in_sizes[0] / INC;
    const int total4 = (n * OUTC) / 4;

    cudaFuncSetAttribute(k_gemm, cudaFuncAttributeMaxDynamicSharedMemorySize, SMEM_TOTAL);

    k_prep<<<2048, 256>>>(mask, (float4*)out, (const float4*)feats, n, total4);
    k_conv_w<<<KOFF, 256>>>(W);

    dim3 grid((n + TP - 1) / TP, KOFF);
    k_gemm<<<grid, 256, SMEM_TOTAL>>>(in_idx, out_idx, out, n);

    k_stats<<<1184, 256>>>((const float4*)out, total4);
    k_bn<<<2048, 256>>>((float4*)out, gamma, beta, total4, 1.0f / (float)n);
}

// round 12
// speedup vs baseline: 2.3718x; 1.0072x over previous
#include <cuda_runtime.h>
#include <cuda_bf16.h>
#include <cstdint>

#define INC    64
#define OUTC   64
#define KOFF   27
#define TP     256
#define NMAX   400000
#define BN_EPS 1e-5f

__device__ int   g_counts[KOFF];
__device__ float g_sum[OUTC];
__device__ float g_sumsq[OUTC];

// precomputed bf16 hi/lo operands
__device__ uint4 FHI4[NMAX * 8];            // feats hi: [row][128B]
__device__ uint4 FLO4[NMAX * 8];            // feats lo
__device__ uint4 WHI4[KOFF * 512];          // W^T hi, SW128-swizzled B tiles (8KB each)
__device__ uint4 WLO4[KOFF * 512];

// ---------------- smem layout ----------------
#define SM_AHI   0
#define SM_ALO   32768
#define SM_BHI   65536
#define SM_BLO   73728
#define SM_DL    81920
#define SMEM_TOTAL (81920 + TP * 4)

#define SWZ128(x) ((x) ^ (((x) >> 3) & 0x70))

static __device__ __forceinline__ uint32_t smem_u32(const void* p) {
    uint32_t a;
    asm("{ .reg .u64 t; cvta.to.shared.u64 t, %1; cvt.u32.u64 %0, t; }" : "=r"(a) : "l"(p));
    return a;
}
static __device__ __forceinline__ void cpasync16(uint32_t dst, const void* src) {
    asm volatile("cp.async.cg.shared.global [%0], [%1], 16;" :: "r"(dst), "l"(src) : "memory");
}
static __device__ __forceinline__ void ldsm4(uint32_t* r, uint32_t addr) {
    asm volatile("ldmatrix.sync.aligned.m8n8.x4.shared.b16 {%0,%1,%2,%3}, [%4];"
                 : "=r"(r[0]), "=r"(r[1]), "=r"(r[2]), "=r"(r[3]) : "r"(addr));
}
static __device__ __forceinline__ void mma_bf16(float* c, const uint32_t* a,
                                                uint32_t b0, uint32_t b1) {
    asm volatile("mma.sync.aligned.m16n8k16.row.col.f32.bf16.bf16.f32 "
                 "{%0,%1,%2,%3}, {%4,%5,%6,%7}, {%8,%9}, {%0,%1,%2,%3};"
                 : "+f"(c[0]), "+f"(c[1]), "+f"(c[2]), "+f"(c[3])
                 : "r"(a[0]), "r"(a[1]), "r"(a[2]), "r"(a[3]), "r"(b0), "r"(b1));
}
static __device__ __forceinline__ void split_bf16(float x, unsigned short& h, unsigned short& l) {
    __nv_bfloat16 hb = __float2bfloat16_rn(x);
    float r = x - __bfloat162float(hb);
    __nv_bfloat16 lb = __float2bfloat16_rn(r);
    h = __bfloat16_as_ushort(hb);
    l = __bfloat16_as_ushort(lb);
}

// ---------- K0: counts + zero BN stats + zero output + feats hi/lo split ----------
__global__ void k_prep(const float* __restrict__ mask, float4* __restrict__ out,
                       const float4* __restrict__ feats4, int n, int total4) {
    const int tid = threadIdx.x;
    if (blockIdx.x == 0) {
        if (tid < OUTC) { g_sum[tid] = 0.f; g_sumsq[tid] = 0.f; }
        if (tid < KOFF) {
            const float* m = mask + (size_t)tid * n;
            int lo = 0, hi = n;
            while (lo < hi) {
                int mid = (lo + hi) >> 1;
                if (m[mid] > 0.5f) lo = mid + 1; else hi = mid;
            }
            g_counts[tid] = lo;
        }
    }
    const int gstride = gridDim.x * blockDim.x;
    for (int i = blockIdx.x * blockDim.x + tid; i < total4; i += gstride)
        out[i] = make_float4(0.f, 0.f, 0.f, 0.f);

    uint2* fh = (uint2*)FHI4;
    uint2* fl = (uint2*)FLO4;
    const int nf4 = n * 16;
    for (int i = blockIdx.x * blockDim.x + tid; i < nf4; i += gstride) {
        float4 v = feats4[i];
        unsigned short h0, h1, h2, h3, l0, l1, l2, l3;
        split_bf16(v.x, h0, l0); split_bf16(v.y, h1, l1);
        split_bf16(v.z, h2, l2); split_bf16(v.w, h3, l3);
        fh[i] = make_uint2((uint32_t)h0 | ((uint32_t)h1 << 16),
                           (uint32_t)h2 | ((uint32_t)h3 << 16));
        fl[i] = make_uint2((uint32_t)l0 | ((uint32_t)l1 << 16),
                           (uint32_t)l2 | ((uint32_t)l3 << 16));
    }
}

// ---------- K0c: W -> transposed, hi/lo, SW128-swizzled B tiles ----------
__global__ void k_conv_w(const float* __restrict__ W) {
    const int k   = blockIdx.x;
    const int tid = threadIdx.x;
    const int c   = tid >> 2;
    const int kq  = (tid & 3) * 16;
    const float* Wk = W + (size_t)k * INC * OUTC;
    char* wh = (char*)(WHI4 + k * 512);
    char* wl = (char*)(WLO4 + k * 512);
    #pragma unroll
    for (int j0 = 0; j0 < 16; j0 += 4) {
        float x0 = Wk[(size_t)(kq + j0 + 0) * OUTC + c];
        float x1 = Wk[(size_t)(kq + j0 + 1) * OUTC + c];
        float x2 = Wk[(size_t)(kq + j0 + 2) * OUTC + c];
        float x3 = Wk[(size_t)(kq + j0 + 3) * OUTC + c];
        unsigned short h0, h1, h2, h3, l0, l1, l2, l3;
        split_bf16(x0, h0, l0); split_bf16(x1, h1, l1);
        split_bf16(x2, h2, l2); split_bf16(x3, h3, l3);
        uint32_t off = SWZ128((uint32_t)(c * 128 + (kq + j0) * 2));
        *(uint2*)(wh + off) = make_uint2((uint32_t)h0 | ((uint32_t)h1 << 16),
                                         (uint32_t)h2 | ((uint32_t)h3 << 16));
        *(uint2*)(wl + off) = make_uint2((uint32_t)l0 | ((uint32_t)l1 << 16),
                                         (uint32_t)l2 | ((uint32_t)l3 << 16));
    }
}

// ---------- K1: HMMA scatter GEMM (4 warps, 64-pair warp tiles) ----------
__global__ __launch_bounds__(128)
void k_gemm(const int* __restrict__ in_idx, const int* __restrict__ out_idx,
            float* __restrict__ out, int n)
{
    extern __shared__ char smem[];
    const int k    = blockIdx.y;
    const int base = blockIdx.x * TP;
    const int cnt  = g_counts[k];
    if (base >= cnt) return;
    const int np = min(TP, cnt - base);

    const uint32_t sb = smem_u32(smem);
    const int tid = threadIdx.x, wid = tid >> 5, lane = tid & 31;
    const size_t kbase = (size_t)k * n + base;
    int* dl = (int*)(smem + SM_DL);

    // --- B tiles via cp.async (8KB hi + 8KB lo, pre-swizzled) ---
    {
        const uint4* wh = WHI4 + k * 512;
        const uint4* wl = WLO4 + k * 512;
        #pragma unroll
        for (int j = 0; j < 4; j++) {
            cpasync16(sb + SM_BHI + (tid + j * 128) * 16, wh + tid + j * 128);
            cpasync16(sb + SM_BLO + (tid + j * 128) * 16, wl + tid + j * 128);
        }
    }

    // --- gather A via cp.async: 2 pairs/thread; rows >= np stay garbage ---
    {
        #pragma unroll
        for (int g = 0; g < 2; g++) {
            const int p = tid + g * 128;
            if (p < np) {
                const int src = in_idx[kbase + p];
                dl[p] = out_idx[kbase + p];
                const uint4* fh = FHI4 + (size_t)src * 8;
                const uint4* fl = FLO4 + (size_t)src * 8;
                #pragma unroll
                for (int j = 0; j < 8; j++) {
                    uint32_t off = SWZ128((uint32_t)(p * 128 + j * 16));
                    cpasync16(sb + SM_AHI + off, fh + j);
                    cpasync16(sb + SM_ALO + off, fl + j);
                }
            }
        }
    }
    asm volatile("cp.async.commit_group;" ::: "memory");
    asm volatile("cp.async.wait_group 0;" ::: "memory");
    __syncthreads();

    // --- compute: warp = 64 pairs x 64 cols; 3-pass hi/lo mma.sync ---
    const int pm = wid * 64;
    float acc[4][8][4];
    #pragma unroll
    for (int mb = 0; mb < 4; mb++)
        #pragma unroll
        for (int i = 0; i < 8; i++)
            #pragma unroll
            for (int j = 0; j < 4; j++) acc[mb][i][j] = 0.f;

    const int lm = lane >> 3;
    const int lr = lane & 7;

    #pragma unroll
    for (int ks = 0; ks < 4; ks++) {
        uint32_t ah[4][4], al[4][4];
        #pragma unroll
        for (int mb = 0; mb < 4; mb++) {
            const int arow = pm + mb * 16 + lr + (lm & 1) * 8;
            const int acol = ks * 16 + (lm >> 1) * 8;
            const uint32_t aoff = SWZ128((uint32_t)(arow * 128 + acol * 2));
            ldsm4(ah[mb], sb + SM_AHI + aoff);
            ldsm4(al[mb], sb + SM_ALO + aoff);
        }
        #pragma unroll
        for (int nn = 0; nn < 4; nn++) {
            const int brow = nn * 16 + lr + (lm >> 1) * 8;
            const int bcol = ks * 16 + (lm & 1) * 8;
            const uint32_t boff = SWZ128((uint32_t)(brow * 128 + bcol * 2));
            uint32_t bh[4], bl[4];
            ldsm4(bh, sb + SM_BHI + boff);
            ldsm4(bl, sb + SM_BLO + boff);
            #pragma unroll
            for (int mb = 0; mb < 4; mb++) {
                mma_bf16(acc[mb][2 * nn + 0], ah[mb], bh[0], bh[1]);
                mma_bf16(acc[mb][2 * nn + 1], ah[mb], bh[2], bh[3]);
                mma_bf16(acc[mb][2 * nn + 0], al[mb], bh[0], bh[1]);
                mma_bf16(acc[mb][2 * nn + 1], al[mb], bh[2], bh[3]);
                mma_bf16(acc[mb][2 * nn + 0], ah[mb], bl[0], bl[1]);
                mma_bf16(acc[mb][2 * nn + 1], ah[mb], bl[2], bl[3]);
            }
        }
    }

    // --- direct register scatter: red.v2 per fragment pair ---
    {
        #pragma unroll
        for (int mb = 0; mb < 4; mb++) {
            const int r0 = pm + mb * 16 + (lane >> 2);
            #pragma unroll
            for (int half = 0; half < 2; half++) {
                const int r = r0 + half * 8;
                if (r < np) {
                    const int dst = dl[r];
                    float* o = out + (size_t)dst * OUTC + (lane & 3) * 2;
                    #pragma unroll
                    for (int j = 0; j < 8; j++) {
                        const int col = (j >> 1) * 16 + (j & 1) * 8;
                        asm volatile("red.global.add.v2.f32 [%0], {%1,%2};"
                                     :: "l"(o + col),
                                        "f"(acc[mb][j][2 * half]),
                                        "f"(acc[mb][j][2 * half + 1]) : "memory");
                    }
                }
            }
        }
    }
}

// ---------- K2: per-channel sum / sumsq ----------
__global__ __launch_bounds__(256)
void k_stats(const float4* __restrict__ out4, int total4) {
    const int tid = threadIdx.x;
    const int cg  = (tid & 15) * 4;
    float s0 = 0.f, s1 = 0.f, s2 = 0.f, s3 = 0.f;
    float q0 = 0.f, q1 = 0.f, q2 = 0.f, q3 = 0.f;
    const int stride = gridDim.x * 256;
    int i = blockIdx.x * 256 + tid;
    for (; i + 3 * stride < total4; i += 4 * stride) {
        float4 v0 = out4[i];
        float4 v1 = out4[i + stride];
        float4 v2 = out4[i + 2 * stride];
        float4 v3 = out4[i + 3 * stride];
        s0 += v0.x + v1.x + v2.x + v3.x;
        s1 += v0.y + v1.y + v2.y + v3.y;
        s2 += v0.z + v1.z + v2.z + v3.z;
        s3 += v0.w + v1.w + v2.w + v3.w;
        q0 += v0.x*v0.x + v1.x*v1.x + v2.x*v2.x + v3.x*v3.x;
        q1 += v0.y*v0.y + v1.y*v1.y + v2.y*v2.y + v3.y*v3.y;
        q2 += v0.z*v0.z + v1.z*v1.z + v2.z*v2.z + v3.z*v3.z;
        q3 += v0.w*v0.w + v1.w*v1.w + v2.w*v2.w + v3.w*v3.w;
    }
    for (; i < total4; i += stride) {
        float4 v = out4[i];
        s0 += v.x; s1 += v.y; s2 += v.z; s3 += v.w;
        q0 += v.x*v.x; q1 += v.y*v.y; q2 += v.z*v.z; q3 += v.w*v.w;
    }
    __shared__ float ssum[OUTC];
    __shared__ float ssq[OUTC];
    if (tid < OUTC) { ssum[tid] = 0.f; ssq[tid] = 0.f; }
    __syncthreads();
    atomicAdd(&ssum[cg + 0], s0); atomicAdd(&ssq[cg + 0], q0);
    atomicAdd(&ssum[cg + 1], s1); atomicAdd(&ssq[cg + 1], q1);
    atomicAdd(&ssum[cg + 2], s2); atomicAdd(&ssq[cg + 2], q2);
    atomicAdd(&ssum[cg + 3], s3); atomicAdd(&ssq[cg + 3], q3);
    __syncthreads();
    if (tid < OUTC) {
        atomicAdd(&g_sum[tid],   ssum[tid]);
        atomicAdd(&g_sumsq[tid], ssq[tid]);
    }
}

// ---------- K3: BatchNorm + ReLU ----------
__global__ __launch_bounds__(256)
void k_bn(float4* __restrict__ out,
          const float* __restrict__ gamma, const float* __restrict__ beta,
          int total4, float invN)
{
    const int tid = threadIdx.x;
    const int cg  = (tid & 15) * 4;
    float mean[4], scl[4], bet[4];
    #pragma unroll
    for (int j = 0; j < 4; j++) {
        int c = cg + j;
        float m = g_sum[c] * invN;
        float var = g_sumsq[c] * invN - m * m;
        mean[j] = m;
        scl[j] = rsqrtf(var + BN_EPS) * gamma[c];
        bet[j] = beta[c];
    }
    const int stride = gridDim.x * 256;
    for (int i = blockIdx.x * 256 + tid; i < total4; i += stride) {
        float4 v = out[i];
        v.x = fmaxf((v.x - mean[0]) * scl[0] + bet[0], 0.f);
        v.y = fmaxf((v.y - mean[1]) * scl[1] + bet[1], 0.f);
        v.z = fmaxf((v.z - mean[2]) * scl[2] + bet[2], 0.f);
        v.w = fmaxf((v.w - mean[3]) * scl[3] + bet[3], 0.f);
        out[i] = v;
    }
}

// ---------- launch ----------
extern "C" void kernel_launch(void* const* d_in, const int* in_sizes, int n_in,
                              void* d_out, int out_size)
{
    const float* feats   = (const float*)d_in[0];
    const float* W       = (const float*)d_in[1];
    const float* gamma   = (const float*)d_in[2];
    const float* beta    = (const float*)d_in[3];
    const float* mask    = (const float*)d_in[4];
    const int*   in_idx  = (const int*)d_in[5];
    const int*   out_idx = (const int*)d_in[6];
    float*       out     = (float*)d_out;

    const int n = in_sizes[0] / INC;
    const int total4 = (n * OUTC) / 4;

    cudaFuncSetAttribute(k_gemm, cudaFuncAttributeMaxDynamicSharedMemorySize, SMEM_TOTAL);

    k_prep<<<2048, 256>>>(mask, (float4*)out, (const float4*)feats, n, total4);
    k_conv_w<<<KOFF, 256>>>(W);

    dim3 grid((n + TP - 1) / TP, KOFF);
    k_gemm<<<grid, 128, SMEM_TOTAL>>>(in_idx, out_idx, out, n);

    k_stats<<<1184, 256>>>((const float4*)out, total4);
    k_bn<<<2048, 256>>>((float4*)out, gamma, beta, total4, 1.0f / (float)n);
}